// round 4
// baseline (speedup 1.0000x reference)
#include <cuda_runtime.h>
#include <cuda_fp16.h>

#define NMAX 100000
#define EMAX 1600000
#define HID 64
#define HASH_BITS 22
#define HASH_SIZE (1u << HASH_BITS)
#define HASH_MASK (HASH_SIZE - 1u)
#define HEMPTY 0xFFFFFFFFFFFFFFFFull
#define SCAN_FLAG (1ull << 63)

// ---------------- scratch (device globals: allocation-free rule) ----------------
__device__ int    g_deg[NMAX];
__device__ int    g_cnt[NMAX];
__device__ int    g_rowptr[NMAX + 1];
__device__ int    g_cursor[NMAX];
__device__ int    g_col[EMAX];
__device__ float  g_norm[NMAX];
__device__ unsigned long long g_scanstate[128];
__device__ unsigned long long g_hash[HASH_SIZE];
__device__ __half g_h1[(size_t)NMAX * HID];   // lin1 out (fp16, gather table for agg1)
__device__ float  g_mid[(size_t)NMAX * HID];  // agg1 out (fp32, lin2 input)
__device__ __half g_h2[(size_t)NMAX * HID];   // lin2 out (fp16, gather table for agg2)
__device__ float4 g_pq[NMAX];

// ---------------- init: zero deg/cnt/scanstate, clear hash ----------------
__global__ void init_kernel(int n) {
    int gtid = blockIdx.x * blockDim.x + threadIdx.x;
    int stride = gridDim.x * blockDim.x;
    for (int i = gtid; i < n; i += stride) { g_deg[i] = 0; g_cnt[i] = 0; }
    if (gtid < 128) g_scanstate[gtid] = 0ull;
    ulonglong2* h2 = (ulonglong2*)g_hash;
    ulonglong2 ev; ev.x = HEMPTY; ev.y = HEMPTY;
    for (unsigned j = gtid; j < HASH_SIZE / 2; j += stride) h2[j] = ev;
}

// ---------------- FUSED: lin1 (quarter-row/thread) + hist/distinct, roles interleaved ----------------
__global__ __launch_bounds__(256) void fused_lin1_hist_kernel(
    const float* __restrict__ x, const float* __restrict__ W,
    const float* __restrict__ b,
    const int* __restrict__ src, const int* __restrict__ dst,
    __half* __restrict__ out, int n, int e, int nbLin, int T)
{
    __shared__ float Ws[128 * HID];   // 32 KB (GEMM blocks only use it)
    __shared__ float bs[HID];

    int bid = blockIdx.x;
    int cumPrev = (int)(((long long)bid * nbLin) / T);
    int cumCur  = (int)(((long long)(bid + 1) * nbLin) / T);

    if (cumCur > cumPrev) {
        // -------- GEMM branch: 4 threads per row, 16 cols each --------
        for (int i = threadIdx.x; i < (128 * HID) / 4; i += 256)
            ((float4*)Ws)[i] = ((const float4*)W)[i];
        if (threadIdx.x < HID) bs[threadIdx.x] = b[threadIdx.x];
        __syncthreads();

        int gid = cumPrev * 256 + threadIdx.x;
        int row = gid >> 2;
        int cbase = (gid & 3) * 16;
        if (row >= n) return;

        float acc[16];
#pragma unroll
        for (int c = 0; c < 16; c++) acc[c] = 0.f;

        const float4* xr = (const float4*)(x + (size_t)row * 128);
#pragma unroll
        for (int k4 = 0; k4 < 32; k4++) {
            float4 xv = xr[k4];
            float xk[4] = {xv.x, xv.y, xv.z, xv.w};
#pragma unroll
            for (int kk = 0; kk < 4; kk++) {
                float xs = xk[kk];
                const float4* wr = (const float4*)(Ws + (k4 * 4 + kk) * HID + cbase);
#pragma unroll
                for (int c = 0; c < 4; c++) {
                    float4 w = wr[c];
                    acc[4 * c + 0] += xs * w.x;
                    acc[4 * c + 1] += xs * w.y;
                    acc[4 * c + 2] += xs * w.z;
                    acc[4 * c + 3] += xs * w.w;
                }
            }
        }
        __half2 hv[8];
#pragma unroll
        for (int c = 0; c < 8; c++)
            hv[c] = __floats2half2_rn(acc[2 * c] + bs[cbase + 2 * c],
                                      acc[2 * c + 1] + bs[cbase + 2 * c + 1]);
        uint4* o = (uint4*)(out + (size_t)row * HID + cbase);
        o[0] = ((uint4*)hv)[0];
        o[1] = ((uint4*)hv)[1];
    } else {
        // -------- histogram + distinct branch, 4 edges per thread --------
        int histBid = bid - cumCur;
        int i0 = (histBid * 256 + threadIdx.x) * 4;
        if (i0 >= e) return;
        int ss[4], dd[4];
        int cnt;
        if (i0 + 4 <= e) {
            int4 s4 = *(const int4*)(src + i0);
            int4 d4 = *(const int4*)(dst + i0);
            ss[0] = s4.x; ss[1] = s4.y; ss[2] = s4.z; ss[3] = s4.w;
            dd[0] = d4.x; dd[1] = d4.y; dd[2] = d4.z; dd[3] = d4.w;
            cnt = 4;
        } else {
            cnt = e - i0;
            for (int t = 0; t < cnt; t++) { ss[t] = src[i0 + t]; dd[t] = dst[i0 + t]; }
        }
        for (int t = 0; t < cnt; t++) {
            int s = ss[t], d = dd[t];
            atomicAdd(&g_deg[d], 1);
            if (s == d) continue;  // merges with diagonal in coalesce
            unsigned long long key =
                ((unsigned long long)(unsigned)d << 32) | (unsigned)s;
            unsigned h = (unsigned)((key * 0x9E3779B97F4A7C15ull) >> (64 - HASH_BITS));
            for (;;) {
                unsigned long long old = atomicCAS(&g_hash[h], HEMPTY, key);
                if (old == HEMPTY) { atomicAdd(&g_cnt[d], 1); break; }
                if (old == key) break;
                h = (h + 1) & HASH_MASK;
            }
        }
    }
}

// ---------------- single-pass chained scan (decoupled lookback) + cursor + norm ----------------
__global__ void scan_kernel(int n, int nb) {
    __shared__ int sh[1024];
    __shared__ int s_prefix;
    int t = threadIdx.x;
    int bid = blockIdx.x;
    int i = bid * 1024 + t;
    int v = (i < n) ? g_deg[i] : 0;
    sh[t] = v;
    __syncthreads();
    for (int off = 1; off < 1024; off <<= 1) {
        int u = (t >= off) ? sh[t - off] : 0;
        __syncthreads();
        sh[t] += u;
        __syncthreads();
    }
    int incl = sh[t];
    int total = sh[1023];

    if (t == 0) {
        unsigned long long prefix = 0ull;
        if (bid > 0) {
            unsigned long long s;
            do {
                s = atomicAdd(&g_scanstate[bid - 1], 0ull);
            } while (!(s & SCAN_FLAG));
            prefix = s & ~SCAN_FLAG;
        }
        atomicExch(&g_scanstate[bid],
                   SCAN_FLAG | (prefix + (unsigned long long)total));
        s_prefix = (int)prefix;
    }
    __syncthreads();
    int pre = s_prefix;

    if (i < n) {
        int r = pre + incl - v;
        g_rowptr[i] = r;
        g_cursor[i] = r;
        g_norm[i] = 1.0f / (float)(1 + g_cnt[i]);
    }
    if (bid == nb - 1 && t == 1023) g_rowptr[n] = pre + total;
}

// ---------------- CSR scatter (4 edges/thread) ----------------
__global__ void scatter_kernel(const int* __restrict__ src,
                               const int* __restrict__ dst, int e) {
    int i0 = (blockIdx.x * blockDim.x + threadIdx.x) * 4;
    if (i0 >= e) return;
    if (i0 + 4 <= e) {
        int4 s4 = *(const int4*)(src + i0);
        int4 d4 = *(const int4*)(dst + i0);
        int p0 = atomicAdd(&g_cursor[d4.x], 1); g_col[p0] = s4.x;
        int p1 = atomicAdd(&g_cursor[d4.y], 1); g_col[p1] = s4.y;
        int p2 = atomicAdd(&g_cursor[d4.z], 1); g_col[p2] = s4.z;
        int p3 = atomicAdd(&g_cursor[d4.w], 1); g_col[p3] = s4.w;
    } else {
        for (int i = i0; i < e; i++) {
            int p = atomicAdd(&g_cursor[dst[i]], 1);
            g_col[p] = src[i];
        }
    }
}

// ---------------- layer-1 aggregation + combine + relu (fp16 gather, fp32 accumulate) ----------------
__global__ void agg1_kernel(const __half* __restrict__ h,
                            const float* __restrict__ wpan,
                            float* __restrict__ out, int n) {
    int wid = (blockIdx.x * blockDim.x + threadIdx.x) >> 5;
    int lane = threadIdx.x & 31;
    if (wid >= n) return;
    int lo = g_rowptr[wid], hi = g_rowptr[wid + 1];
    const __half2* h2 = (const __half2*)h;
    float ax = 0.f, ay = 0.f;
    int j = lo;
    for (; j + 3 < hi; j += 4) {
        int s0 = g_col[j], s1 = g_col[j + 1], s2 = g_col[j + 2], s3 = g_col[j + 3];
        float2 f0 = __half22float2(h2[(size_t)s0 * 32 + lane]);
        float2 f1 = __half22float2(h2[(size_t)s1 * 32 + lane]);
        float2 f2 = __half22float2(h2[(size_t)s2 * 32 + lane]);
        float2 f3 = __half22float2(h2[(size_t)s3 * 32 + lane]);
        ax += f0.x + f1.x + f2.x + f3.x;
        ay += f0.y + f1.y + f2.y + f3.y;
    }
    for (; j < hi; j++) {
        float2 f = __half22float2(h2[(size_t)g_col[j] * 32 + lane]);
        ax += f.x; ay += f.y;
    }
    float w0 = wpan[0];
    float w01 = w0 * wpan[1];
    float nm = g_norm[wid];
    float2 hv = __half22float2(h2[(size_t)wid * 32 + lane]);
    float ox = fmaxf(nm * (w0 * hv.x + w01 * ax), 0.f);
    float oy = fmaxf(nm * (w0 * hv.y + w01 * ay), 0.f);
    ((float2*)out)[(size_t)wid * 32 + lane] = make_float2(ox, oy);
}

// ---------------- layer-2 linear: g_h2[n,64] = fp16( mid[n,64] @ W2 + b2 ) ----------------
__global__ __launch_bounds__(256) void lin2_kernel(const float* __restrict__ x,
                                                   const float* __restrict__ W,
                                                   const float* __restrict__ b,
                                                   __half* __restrict__ out, int n) {
    __shared__ float Ws[64 * HID];   // 16 KB
    __shared__ float bs[HID];
    for (int i = threadIdx.x; i < (64 * HID) / 4; i += 256)
        ((float4*)Ws)[i] = ((const float4*)W)[i];
    if (threadIdx.x < HID) bs[threadIdx.x] = b[threadIdx.x];
    __syncthreads();

    int gid = blockIdx.x * 256 + threadIdx.x;
    int row = gid >> 1;
    int cbase = (gid & 1) * 32;
    if (row >= n) return;

    float acc[32];
#pragma unroll
    for (int c = 0; c < 32; c++) acc[c] = 0.f;

    const float4* xr = (const float4*)(x + (size_t)row * 64);
#pragma unroll
    for (int k4 = 0; k4 < 16; k4++) {
        float4 xv = xr[k4];
        float xk[4] = {xv.x, xv.y, xv.z, xv.w};
#pragma unroll
        for (int kk = 0; kk < 4; kk++) {
            float xs = xk[kk];
            const float4* wr = (const float4*)(Ws + (k4 * 4 + kk) * HID + cbase);
#pragma unroll
            for (int c = 0; c < 8; c++) {
                float4 w = wr[c];
                acc[4 * c + 0] += xs * w.x;
                acc[4 * c + 1] += xs * w.y;
                acc[4 * c + 2] += xs * w.z;
                acc[4 * c + 3] += xs * w.w;
            }
        }
    }
    __half2 hv[16];
#pragma unroll
    for (int c = 0; c < 16; c++)
        hv[c] = __floats2half2_rn(acc[2 * c] + bs[cbase + 2 * c],
                                  acc[2 * c + 1] + bs[cbase + 2 * c + 1]);
    uint4* o = (uint4*)(out + (size_t)row * HID + cbase);
    o[0] = ((uint4*)hv)[0];
    o[1] = ((uint4*)hv)[1];
    o[2] = ((uint4*)hv)[2];
    o[3] = ((uint4*)hv)[3];
}

// ---------------- FUSED layer-2 aggregation + classifier halves (fp16 gather) ----------------
__global__ void agg2pq_kernel(const __half* __restrict__ h,
                              const float* __restrict__ wpan,
                              const float* __restrict__ wc, int n) {
    int wid = (blockIdx.x * blockDim.x + threadIdx.x) >> 5;
    int lane = threadIdx.x & 31;
    if (wid >= n) return;
    int lo = g_rowptr[wid], hi = g_rowptr[wid + 1];
    const __half2* h2 = (const __half2*)h;
    float ax = 0.f, ay = 0.f;
    int j = lo;
    for (; j + 3 < hi; j += 4) {
        int s0 = g_col[j], s1 = g_col[j + 1], s2 = g_col[j + 2], s3 = g_col[j + 3];
        float2 f0 = __half22float2(h2[(size_t)s0 * 32 + lane]);
        float2 f1 = __half22float2(h2[(size_t)s1 * 32 + lane]);
        float2 f2 = __half22float2(h2[(size_t)s2 * 32 + lane]);
        float2 f3 = __half22float2(h2[(size_t)s3 * 32 + lane]);
        ax += f0.x + f1.x + f2.x + f3.x;
        ay += f0.y + f1.y + f2.y + f3.y;
    }
    for (; j < hi; j++) {
        float2 f = __half22float2(h2[(size_t)g_col[j] * 32 + lane]);
        ax += f.x; ay += f.y;
    }
    float w0 = wpan[0];
    float w01 = w0 * wpan[1];
    float nm = g_norm[wid];
    float2 hv = __half22float2(h2[(size_t)wid * 32 + lane]);
    float ox = nm * (w0 * hv.x + w01 * ax);   // h_final[2*lane]
    float oy = nm * (w0 * hv.y + w01 * ay);   // h_final[2*lane+1]

    // wc is [128,2] row-major; rows 0..63 = src half, 64..127 = dst half
    int c0 = 2 * lane, c1 = 2 * lane + 1;
    float p0 = ox * __ldg(&wc[c0 * 2 + 0]) + oy * __ldg(&wc[c1 * 2 + 0]);
    float p1 = ox * __ldg(&wc[c0 * 2 + 1]) + oy * __ldg(&wc[c1 * 2 + 1]);
    float q0 = ox * __ldg(&wc[(64 + c0) * 2 + 0]) + oy * __ldg(&wc[(64 + c1) * 2 + 0]);
    float q1 = ox * __ldg(&wc[(64 + c0) * 2 + 1]) + oy * __ldg(&wc[(64 + c1) * 2 + 1]);
#pragma unroll
    for (int off = 16; off > 0; off >>= 1) {
        p0 += __shfl_down_sync(0xffffffffu, p0, off);
        p1 += __shfl_down_sync(0xffffffffu, p1, off);
        q0 += __shfl_down_sync(0xffffffffu, q0, off);
        q1 += __shfl_down_sync(0xffffffffu, q1, off);
    }
    if (lane == 0) g_pq[wid] = make_float4(p0, p1, q0, q1);
}

// ---------------- per-edge output (4 edges/thread) ----------------
__global__ void edge_kernel(const int* __restrict__ src,
                            const int* __restrict__ dst,
                            const float* __restrict__ bc,
                            float* __restrict__ out, int e) {
    int i0 = (blockIdx.x * blockDim.x + threadIdx.x) * 4;
    if (i0 >= e) return;
    float b0 = __ldg(&bc[0]), b1 = __ldg(&bc[1]);
    if (i0 + 4 <= e) {
        int4 s4 = *(const int4*)(src + i0);
        int4 d4 = *(const int4*)(dst + i0);
        float4 pa = g_pq[s4.x], qa = g_pq[d4.x];
        float4 pb = g_pq[s4.y], qb = g_pq[d4.y];
        float4 pc = g_pq[s4.z], qc = g_pq[d4.z];
        float4 pd = g_pq[s4.w], qd = g_pq[d4.w];
        float4 o0, o1;
        o0.x = pa.x + qa.z + b0; o0.y = pa.y + qa.w + b1;
        o0.z = pb.x + qb.z + b0; o0.w = pb.y + qb.w + b1;
        o1.x = pc.x + qc.z + b0; o1.y = pc.y + qc.w + b1;
        o1.z = pd.x + qd.z + b0; o1.w = pd.y + qd.w + b1;
        ((float4*)(out + (size_t)i0 * 2))[0] = o0;
        ((float4*)(out + (size_t)i0 * 2))[1] = o1;
    } else {
        for (int i = i0; i < e; i++) {
            float4 ps = g_pq[src[i]];
            float4 qd = g_pq[dst[i]];
            ((float2*)out)[i] = make_float2(ps.x + qd.z + b0, ps.y + qd.w + b1);
        }
    }
}

// ---------------- launch ----------------
extern "C" void kernel_launch(void* const* d_in, const int* in_sizes, int n_in,
                              void* d_out, int out_size) {
    const float* x   = (const float*)d_in[0];
    const int*   ei  = (const int*)d_in[1];
    const float* w1  = (const float*)d_in[2];
    const float* b1  = (const float*)d_in[3];
    const float* p1  = (const float*)d_in[4];  // w1_pan
    const float* w2  = (const float*)d_in[5];
    const float* b2  = (const float*)d_in[6];
    const float* p2  = (const float*)d_in[7];  // w2_pan
    const float* wc  = (const float*)d_in[8];
    const float* bc  = (const float*)d_in[9];
    float* out = (float*)d_out;

    int n = in_sizes[0] / 128;
    int e = in_sizes[1] / 2;
    const int* src = ei;
    const int* dst = ei + e;

    __half* h1 = nullptr; __half* h2 = nullptr; float* mid = nullptr;
    cudaGetSymbolAddress((void**)&h1, g_h1);
    cudaGetSymbolAddress((void**)&h2, g_h2);
    cudaGetSymbolAddress((void**)&mid, g_mid);

    int nb1024 = (n + 1023) / 1024;
    int ebv = (e + 1023) / 1024;               // 4 edges/thread, 256 threads
    int nbLin1 = (4 * n + 255) / 256;          // quarter-row lin1 blocks
    int T = nbLin1 + ebv;

    init_kernel<<<2048, 256>>>(n);
    fused_lin1_hist_kernel<<<T, 256>>>(x, w1, b1, src, dst, h1, n, e, nbLin1, T);
    scan_kernel<<<nb1024, 1024>>>(n, nb1024);
    scatter_kernel<<<ebv, 256>>>(src, dst, e);

    agg1_kernel<<<(n * 32 + 255) / 256, 256>>>(h1, p1, mid, n);        // layer-1 agg + relu
    lin2_kernel<<<(2 * n + 255) / 256, 256>>>(mid, w2, b2, h2, n);     // layer-2 lin
    agg2pq_kernel<<<(n * 32 + 255) / 256, 256>>>(h2, p2, wc, n);       // layer-2 agg + pq
    edge_kernel<<<ebv, 256>>>(src, dst, bc, out, e);
}

// round 5
// speedup vs baseline: 1.4807x; 1.4807x over previous
#include <cuda_runtime.h>
#include <cuda_fp16.h>

#define NMAX 100000
#define EMAX 1600000
#define HID 64
#define HASH_BITS 22
#define HASH_SIZE (1u << HASH_BITS)
#define HASH_MASK (HASH_SIZE - 1u)
#define HEMPTY 0xFFFFFFFFFFFFFFFFull

// ---------------- scratch (device globals: allocation-free rule) ----------------
__device__ int    g_deg[NMAX];
__device__ int    g_cnt[NMAX];
__device__ int    g_rowptr[NMAX + 1];
__device__ int    g_cursor[NMAX];
__device__ int    g_bsum[1024];
__device__ int    g_col[EMAX];
__device__ float  g_norm[NMAX];
__device__ unsigned long long g_hash[HASH_SIZE];
__device__ __half g_h1[(size_t)NMAX * HID];   // lin1 out (fp16 gather table)
__device__ float  g_mid[(size_t)NMAX * HID];  // agg1 out (fp32, lin2 input)
__device__ __half g_h2[(size_t)NMAX * HID];   // lin2 out (fp16 gather table)
__device__ float4 g_pq[NMAX];

// ---------------- init: zero deg/cnt, clear hash (vectorized) ----------------
__global__ void init_kernel(int n) {
    int gtid = blockIdx.x * blockDim.x + threadIdx.x;
    int stride = gridDim.x * blockDim.x;
    for (int i = gtid; i < n; i += stride) { g_deg[i] = 0; g_cnt[i] = 0; }
    ulonglong2* h2 = (ulonglong2*)g_hash;
    ulonglong2 ev; ev.x = HEMPTY; ev.y = HEMPTY;
    for (unsigned j = gtid; j < HASH_SIZE / 2; j += stride) h2[j] = ev;
}

// ---------------- FUSED: lin1 (half-row per thread) + hist/distinct (range-partitioned) ----------------
__global__ __launch_bounds__(256) void fused_lin1_hist_kernel(
    const float* __restrict__ x, const float* __restrict__ W,
    const float* __restrict__ b,
    const int* __restrict__ src, const int* __restrict__ dst,
    __half* __restrict__ out, int n, int e, int nbLin)
{
    __shared__ float Ws[128 * HID];   // 32 KB
    __shared__ float bs[HID];

    if (blockIdx.x < nbLin) {
        // -------- GEMM branch: 2 threads per row, 32 cols each --------
        for (int i = threadIdx.x; i < (128 * HID) / 4; i += 256)
            ((float4*)Ws)[i] = ((const float4*)W)[i];
        if (threadIdx.x < HID) bs[threadIdx.x] = b[threadIdx.x];
        __syncthreads();

        int gid = blockIdx.x * 256 + threadIdx.x;
        int row = gid >> 1;
        int half = gid & 1;
        if (row >= n) return;

        float acc[32];
#pragma unroll
        for (int c = 0; c < 32; c++) acc[c] = 0.f;

        const float4* xr = (const float4*)(x + (size_t)row * 128);
        int cbase = half * 32;
#pragma unroll
        for (int k4 = 0; k4 < 32; k4++) {
            float4 xv = xr[k4];
            float xk[4] = {xv.x, xv.y, xv.z, xv.w};
#pragma unroll
            for (int kk = 0; kk < 4; kk++) {
                float xs = xk[kk];
                const float4* wr = (const float4*)(Ws + (k4 * 4 + kk) * HID + cbase);
#pragma unroll
                for (int c = 0; c < 8; c++) {
                    float4 w = wr[c];
                    acc[4 * c + 0] += xs * w.x;
                    acc[4 * c + 1] += xs * w.y;
                    acc[4 * c + 2] += xs * w.z;
                    acc[4 * c + 3] += xs * w.w;
                }
            }
        }
        __half2 hv[16];
#pragma unroll
        for (int c = 0; c < 16; c++)
            hv[c] = __floats2half2_rn(acc[2 * c] + bs[cbase + 2 * c],
                                      acc[2 * c + 1] + bs[cbase + 2 * c + 1]);
        uint4* o = (uint4*)(out + (size_t)row * HID + cbase);
        o[0] = ((uint4*)hv)[0];
        o[1] = ((uint4*)hv)[1];
        o[2] = ((uint4*)hv)[2];
        o[3] = ((uint4*)hv)[3];
    } else {
        // -------- histogram + distinct branch, 4 edges per thread --------
        int bid = blockIdx.x - nbLin;
        int i0 = (bid * 256 + threadIdx.x) * 4;
        if (i0 >= e) return;
        int ss[4], dd[4];
        int cnt;
        if (i0 + 4 <= e) {
            int4 s4 = *(const int4*)(src + i0);
            int4 d4 = *(const int4*)(dst + i0);
            ss[0] = s4.x; ss[1] = s4.y; ss[2] = s4.z; ss[3] = s4.w;
            dd[0] = d4.x; dd[1] = d4.y; dd[2] = d4.z; dd[3] = d4.w;
            cnt = 4;
        } else {
            cnt = e - i0;
            for (int t = 0; t < cnt; t++) { ss[t] = src[i0 + t]; dd[t] = dst[i0 + t]; }
        }
        for (int t = 0; t < cnt; t++) {
            int s = ss[t], d = dd[t];
            atomicAdd(&g_deg[d], 1);
            if (s == d) continue;  // merges with diagonal in coalesce
            unsigned long long key =
                ((unsigned long long)(unsigned)d << 32) | (unsigned)s;
            unsigned h = (unsigned)((key * 0x9E3779B97F4A7C15ull) >> (64 - HASH_BITS));
            for (;;) {
                unsigned long long old = atomicCAS(&g_hash[h], HEMPTY, key);
                if (old == HEMPTY) { atomicAdd(&g_cnt[d], 1); break; }
                if (old == key) break;
                h = (h + 1) & HASH_MASK;
            }
        }
    }
}

// ---------------- scan pass 1: per-block exclusive + block sums ----------------
__global__ void scan1_kernel(int n) {
    __shared__ int sh[1024];
    int t = threadIdx.x;
    int i = blockIdx.x * 1024 + t;
    int v = (i < n) ? g_deg[i] : 0;
    sh[t] = v;
    __syncthreads();
    for (int off = 1; off < 1024; off <<= 1) {
        int u = (t >= off) ? sh[t - off] : 0;
        __syncthreads();
        sh[t] += u;
        __syncthreads();
    }
    if (i < n) g_rowptr[i] = sh[t] - v;
    if (t == 1023) g_bsum[blockIdx.x] = sh[1023];
}

// ---------------- scan pass 2 (fused): inline block-sum prefix + cursor + norm ----------------
__global__ void scan3_kernel(int n, int nb) {
    __shared__ int shp[128], sht[128];
    int t = threadIdx.x;
    if (t < 128) {
        int vp = 0, vt = 0;
        if (t < nb) {
            int bsv = g_bsum[t];
            vt = bsv;
            if (t < (int)blockIdx.x) vp = bsv;
        }
        shp[t] = vp; sht[t] = vt;
    }
    __syncthreads();
    for (int off = 64; off > 0; off >>= 1) {
        if (t < off) { shp[t] += shp[t + off]; sht[t] += sht[t + off]; }
        __syncthreads();
    }
    int prefix = shp[0];

    int i = blockIdx.x * 1024 + t;
    if (i < n) {
        int r = g_rowptr[i] + prefix;
        g_rowptr[i] = r;
        g_cursor[i] = r;
        g_norm[i] = 1.0f / (float)(1 + g_cnt[i]);
    }
    if (blockIdx.x == gridDim.x - 1 && t == 0) g_rowptr[n] = sht[0];
}

// ---------------- CSR scatter (4 edges/thread) ----------------
__global__ void scatter_kernel(const int* __restrict__ src,
                               const int* __restrict__ dst, int e) {
    int i0 = (blockIdx.x * blockDim.x + threadIdx.x) * 4;
    if (i0 >= e) return;
    if (i0 + 4 <= e) {
        int4 s4 = *(const int4*)(src + i0);
        int4 d4 = *(const int4*)(dst + i0);
        int p0 = atomicAdd(&g_cursor[d4.x], 1); g_col[p0] = s4.x;
        int p1 = atomicAdd(&g_cursor[d4.y], 1); g_col[p1] = s4.y;
        int p2 = atomicAdd(&g_cursor[d4.z], 1); g_col[p2] = s4.z;
        int p3 = atomicAdd(&g_cursor[d4.w], 1); g_col[p3] = s4.w;
    } else {
        for (int i = i0; i < e; i++) {
            int p = atomicAdd(&g_cursor[dst[i]], 1);
            g_col[p] = src[i];
        }
    }
}

// ---------------- layer-1 aggregation + combine + relu (fp16 gather, fp32 accumulate) ----------------
__global__ void agg1_kernel(const __half* __restrict__ h,
                            const float* __restrict__ wpan,
                            float* __restrict__ out, int n) {
    int wid = (blockIdx.x * blockDim.x + threadIdx.x) >> 5;
    int lane = threadIdx.x & 31;
    if (wid >= n) return;
    int lo = g_rowptr[wid], hi = g_rowptr[wid + 1];
    const __half2* h2 = (const __half2*)h;
    float ax = 0.f, ay = 0.f;
    int j = lo;
    for (; j + 1 < hi; j += 2) {
        int s0 = g_col[j], s1 = g_col[j + 1];
        float2 f0 = __half22float2(h2[(size_t)s0 * 32 + lane]);
        float2 f1 = __half22float2(h2[(size_t)s1 * 32 + lane]);
        ax += f0.x + f1.x;
        ay += f0.y + f1.y;
    }
    if (j < hi) {
        float2 f = __half22float2(h2[(size_t)g_col[j] * 32 + lane]);
        ax += f.x; ay += f.y;
    }
    float w0 = wpan[0];
    float w01 = w0 * wpan[1];
    float nm = g_norm[wid];
    float2 hv = __half22float2(h2[(size_t)wid * 32 + lane]);
    float ox = fmaxf(nm * (w0 * hv.x + w01 * ax), 0.f);
    float oy = fmaxf(nm * (w0 * hv.y + w01 * ay), 0.f);
    ((float2*)out)[(size_t)wid * 32 + lane] = make_float2(ox, oy);
}

// ---------------- layer-2 linear: h2[n,64] = fp16( mid[n,64] @ W2 + b2 ) ----------------
__global__ __launch_bounds__(256) void lin2_kernel(const float* __restrict__ x,
                                                   const float* __restrict__ W,
                                                   const float* __restrict__ b,
                                                   __half* __restrict__ out, int n) {
    __shared__ float Ws[64 * HID];
    __shared__ float bs[HID];
    for (int i = threadIdx.x; i < (64 * HID) / 4; i += blockDim.x)
        ((float4*)Ws)[i] = ((const float4*)W)[i];
    if (threadIdx.x < HID) bs[threadIdx.x] = b[threadIdx.x];
    __syncthreads();

    int row = blockIdx.x * blockDim.x + threadIdx.x;
    if (row >= n) return;

    float acc[HID];
#pragma unroll
    for (int c = 0; c < HID; c++) acc[c] = 0.f;

    const float4* xr = (const float4*)(x + (size_t)row * 64);
#pragma unroll
    for (int k4 = 0; k4 < 16; k4++) {
        float4 xv = xr[k4];
        float xk[4] = {xv.x, xv.y, xv.z, xv.w};
#pragma unroll
        for (int kk = 0; kk < 4; kk++) {
            float xs = xk[kk];
            const float4* wr = (const float4*)(Ws + (k4 * 4 + kk) * HID);
#pragma unroll
            for (int c = 0; c < HID / 4; c++) {
                float4 w = wr[c];
                acc[4 * c + 0] += xs * w.x;
                acc[4 * c + 1] += xs * w.y;
                acc[4 * c + 2] += xs * w.z;
                acc[4 * c + 3] += xs * w.w;
            }
        }
    }
    __half2 hv[32];
#pragma unroll
    for (int c = 0; c < 32; c++)
        hv[c] = __floats2half2_rn(acc[2 * c] + bs[2 * c],
                                  acc[2 * c + 1] + bs[2 * c + 1]);
    uint4* o = (uint4*)(out + (size_t)row * HID);
#pragma unroll
    for (int c = 0; c < 8; c++) o[c] = ((uint4*)hv)[c];
}

// ---------------- FUSED layer-2 aggregation + classifier halves (fp16 gather) ----------------
__global__ void agg2pq_kernel(const __half* __restrict__ h,
                              const float* __restrict__ wpan,
                              const float* __restrict__ wc, int n) {
    int wid = (blockIdx.x * blockDim.x + threadIdx.x) >> 5;
    int lane = threadIdx.x & 31;
    if (wid >= n) return;
    int lo = g_rowptr[wid], hi = g_rowptr[wid + 1];
    const __half2* h2 = (const __half2*)h;
    float ax = 0.f, ay = 0.f;
    int j = lo;
    for (; j + 1 < hi; j += 2) {
        int s0 = g_col[j], s1 = g_col[j + 1];
        float2 f0 = __half22float2(h2[(size_t)s0 * 32 + lane]);
        float2 f1 = __half22float2(h2[(size_t)s1 * 32 + lane]);
        ax += f0.x + f1.x;
        ay += f0.y + f1.y;
    }
    if (j < hi) {
        float2 f = __half22float2(h2[(size_t)g_col[j] * 32 + lane]);
        ax += f.x; ay += f.y;
    }
    float w0 = wpan[0];
    float w01 = w0 * wpan[1];
    float nm = g_norm[wid];
    float2 hv = __half22float2(h2[(size_t)wid * 32 + lane]);
    float ox = nm * (w0 * hv.x + w01 * ax);   // h_final[2*lane]
    float oy = nm * (w0 * hv.y + w01 * ay);   // h_final[2*lane+1]

    // wc is [128,2] row-major; rows 0..63 = src half, 64..127 = dst half
    int c0 = 2 * lane, c1 = 2 * lane + 1;
    float p0 = ox * __ldg(&wc[c0 * 2 + 0]) + oy * __ldg(&wc[c1 * 2 + 0]);
    float p1 = ox * __ldg(&wc[c0 * 2 + 1]) + oy * __ldg(&wc[c1 * 2 + 1]);
    float q0 = ox * __ldg(&wc[(64 + c0) * 2 + 0]) + oy * __ldg(&wc[(64 + c1) * 2 + 0]);
    float q1 = ox * __ldg(&wc[(64 + c0) * 2 + 1]) + oy * __ldg(&wc[(64 + c1) * 2 + 1]);
#pragma unroll
    for (int off = 16; off > 0; off >>= 1) {
        p0 += __shfl_down_sync(0xffffffffu, p0, off);
        p1 += __shfl_down_sync(0xffffffffu, p1, off);
        q0 += __shfl_down_sync(0xffffffffu, q0, off);
        q1 += __shfl_down_sync(0xffffffffu, q1, off);
    }
    if (lane == 0) g_pq[wid] = make_float4(p0, p1, q0, q1);
}

// ---------------- per-edge output (4 edges/thread) ----------------
__global__ void edge_kernel(const int* __restrict__ src,
                            const int* __restrict__ dst,
                            const float* __restrict__ bc,
                            float* __restrict__ out, int e) {
    int i0 = (blockIdx.x * blockDim.x + threadIdx.x) * 4;
    if (i0 >= e) return;
    float b0 = __ldg(&bc[0]), b1 = __ldg(&bc[1]);
    if (i0 + 4 <= e) {
        int4 s4 = *(const int4*)(src + i0);
        int4 d4 = *(const int4*)(dst + i0);
        float4 pa = g_pq[s4.x], qa = g_pq[d4.x];
        float4 pb = g_pq[s4.y], qb = g_pq[d4.y];
        float4 pc = g_pq[s4.z], qc = g_pq[d4.z];
        float4 pd = g_pq[s4.w], qd = g_pq[d4.w];
        float4 o0, o1;
        o0.x = pa.x + qa.z + b0; o0.y = pa.y + qa.w + b1;
        o0.z = pb.x + qb.z + b0; o0.w = pb.y + qb.w + b1;
        o1.x = pc.x + qc.z + b0; o1.y = pc.y + qc.w + b1;
        o1.z = pd.x + qd.z + b0; o1.w = pd.y + qd.w + b1;
        ((float4*)(out + (size_t)i0 * 2))[0] = o0;
        ((float4*)(out + (size_t)i0 * 2))[1] = o1;
    } else {
        for (int i = i0; i < e; i++) {
            float4 ps = g_pq[src[i]];
            float4 qd = g_pq[dst[i]];
            ((float2*)out)[i] = make_float2(ps.x + qd.z + b0, ps.y + qd.w + b1);
        }
    }
}

// ---------------- launch ----------------
extern "C" void kernel_launch(void* const* d_in, const int* in_sizes, int n_in,
                              void* d_out, int out_size) {
    const float* x   = (const float*)d_in[0];
    const int*   ei  = (const int*)d_in[1];
    const float* w1  = (const float*)d_in[2];
    const float* b1  = (const float*)d_in[3];
    const float* p1  = (const float*)d_in[4];  // w1_pan
    const float* w2  = (const float*)d_in[5];
    const float* b2  = (const float*)d_in[6];
    const float* p2  = (const float*)d_in[7];  // w2_pan
    const float* wc  = (const float*)d_in[8];
    const float* bc  = (const float*)d_in[9];
    float* out = (float*)d_out;

    int n = in_sizes[0] / 128;
    int e = in_sizes[1] / 2;
    const int* src = ei;
    const int* dst = ei + e;

    __half* h1 = nullptr; __half* h2 = nullptr; float* mid = nullptr;
    cudaGetSymbolAddress((void**)&h1, g_h1);
    cudaGetSymbolAddress((void**)&h2, g_h2);
    cudaGetSymbolAddress((void**)&mid, g_mid);

    int nb256 = (n + 255) / 256;
    int nb1024 = (n + 1023) / 1024;
    int ebv = (e / 4 + 255) / 256 + 1;        // 4 edges/thread blocks (covers tail)
    int nbLin = (2 * n + 255) / 256;          // half-row lin1 blocks

    init_kernel<<<2048, 256>>>(n);
    fused_lin1_hist_kernel<<<nbLin + ebv, 256>>>(x, w1, b1, src, dst, h1, n, e, nbLin);
    scan1_kernel<<<nb1024, 1024>>>(n);
    scan3_kernel<<<nb1024, 1024>>>(n, nb1024);
    scatter_kernel<<<ebv, 256>>>(src, dst, e);

    agg1_kernel<<<(n * 32 + 255) / 256, 256>>>(h1, p1, mid, n);       // layer-1 agg + relu
    lin2_kernel<<<nb256, 256>>>(mid, w2, b2, h2, n);                  // layer-2 lin
    agg2pq_kernel<<<(n * 32 + 255) / 256, 256>>>(h2, p2, wc, n);      // layer-2 agg + pq
    edge_kernel<<<ebv, 256>>>(src, dst, bc, out, e);
}

// round 6
// speedup vs baseline: 1.4919x; 1.0076x over previous
#include <cuda_runtime.h>
#include <cuda_fp16.h>

#define NMAX 100000
#define EMAX 1600000
#define HID 64
#define HASH_BITS 22
#define HASH_SIZE (1u << HASH_BITS)
#define HASH_MASK (HASH_SIZE - 1u)
#define HEMPTY 0xFFFFFFFFFFFFFFFFull

// ---------------- packed f32x2 helpers (sm_103a dual-fp32 pipe) ----------------
__device__ __forceinline__ unsigned long long pack2(float lo, float hi) {
    unsigned long long r;
    asm("mov.b64 %0, {%1, %2};" : "=l"(r) : "f"(lo), "f"(hi));
    return r;
}
__device__ __forceinline__ float2 unpack2(unsigned long long v) {
    float lo, hi;
    asm("mov.b64 {%0, %1}, %2;" : "=f"(lo), "=f"(hi) : "l"(v));
    return make_float2(lo, hi);
}
__device__ __forceinline__ unsigned long long fma2(unsigned long long a,
                                                   unsigned long long b,
                                                   unsigned long long c) {
    unsigned long long d;
    asm("fma.rn.f32x2 %0, %1, %2, %3;" : "=l"(d) : "l"(a), "l"(b), "l"(c));
    return d;
}

// ---------------- scratch (device globals: allocation-free rule) ----------------
__device__ int    g_deg[NMAX];
__device__ int    g_cnt[NMAX];
__device__ int    g_rowptr[NMAX + 1];
__device__ int    g_cursor[NMAX];
__device__ int    g_bsum[1024];
__device__ int    g_col[EMAX];
__device__ float  g_norm[NMAX];
__device__ unsigned long long g_hash[HASH_SIZE];
__device__ __half g_h1[(size_t)NMAX * HID];   // lin1 out (fp16 gather table)
__device__ float  g_mid[(size_t)NMAX * HID];  // agg1 out (fp32, lin2 input)
__device__ __half g_h2[(size_t)NMAX * HID];   // lin2 out (fp16 gather table)
__device__ float4 g_pq[NMAX];

// ---------------- init: zero deg/cnt, clear hash (vectorized) ----------------
__global__ void init_kernel(int n) {
    int gtid = blockIdx.x * blockDim.x + threadIdx.x;
    int stride = gridDim.x * blockDim.x;
    for (int i = gtid; i < n; i += stride) { g_deg[i] = 0; g_cnt[i] = 0; }
    ulonglong2* h2 = (ulonglong2*)g_hash;
    ulonglong2 ev; ev.x = HEMPTY; ev.y = HEMPTY;
    for (unsigned j = gtid; j < HASH_SIZE / 2; j += stride) h2[j] = ev;
}

// ---------------- FUSED: lin1 (half-row per thread, f32x2) + hist/distinct ----------------
__global__ __launch_bounds__(256) void fused_lin1_hist_kernel(
    const float* __restrict__ x, const float* __restrict__ W,
    const float* __restrict__ b,
    const int* __restrict__ src, const int* __restrict__ dst,
    __half* __restrict__ out, int n, int e, int nbLin)
{
    __shared__ float Ws[128 * HID];   // 32 KB
    __shared__ float bs[HID];

    if (blockIdx.x < nbLin) {
        // -------- GEMM branch: 2 threads per row, 32 cols each, packed f32x2 --------
        for (int i = threadIdx.x; i < (128 * HID) / 4; i += 256)
            ((float4*)Ws)[i] = ((const float4*)W)[i];
        if (threadIdx.x < HID) bs[threadIdx.x] = b[threadIdx.x];
        __syncthreads();

        int gid = blockIdx.x * 256 + threadIdx.x;
        int row = gid >> 1;
        int half = gid & 1;
        if (row >= n) return;

        unsigned long long acc2[16];   // 16 packed pairs = 32 fp32 accumulators
#pragma unroll
        for (int c = 0; c < 16; c++) acc2[c] = 0ull;

        const float4* xr = (const float4*)(x + (size_t)row * 128);
        int cbase = half * 32;
#pragma unroll
        for (int k4 = 0; k4 < 32; k4++) {
            float4 xv = xr[k4];
            float xk[4] = {xv.x, xv.y, xv.z, xv.w};
#pragma unroll
            for (int kk = 0; kk < 4; kk++) {
                unsigned long long xp = pack2(xk[kk], xk[kk]);
                const ulonglong2* wr =
                    (const ulonglong2*)(Ws + (k4 * 4 + kk) * HID + cbase);
#pragma unroll
                for (int c = 0; c < 8; c++) {
                    ulonglong2 w = wr[c];              // LDS.128 = 2 packed pairs
                    acc2[2 * c + 0] = fma2(xp, w.x, acc2[2 * c + 0]);
                    acc2[2 * c + 1] = fma2(xp, w.y, acc2[2 * c + 1]);
                }
            }
        }
        __half2 hv[16];
#pragma unroll
        for (int c = 0; c < 16; c++) {
            float2 v = unpack2(acc2[c]);
            hv[c] = __floats2half2_rn(v.x + bs[cbase + 2 * c],
                                      v.y + bs[cbase + 2 * c + 1]);
        }
        uint4* o = (uint4*)(out + (size_t)row * HID + cbase);
        o[0] = ((uint4*)hv)[0];
        o[1] = ((uint4*)hv)[1];
        o[2] = ((uint4*)hv)[2];
        o[3] = ((uint4*)hv)[3];
    } else {
        // -------- histogram + distinct branch, 4 edges per thread --------
        int bid = blockIdx.x - nbLin;
        int i0 = (bid * 256 + threadIdx.x) * 4;
        if (i0 >= e) return;
        int ss[4], dd[4];
        int cnt;
        if (i0 + 4 <= e) {
            int4 s4 = *(const int4*)(src + i0);
            int4 d4 = *(const int4*)(dst + i0);
            ss[0] = s4.x; ss[1] = s4.y; ss[2] = s4.z; ss[3] = s4.w;
            dd[0] = d4.x; dd[1] = d4.y; dd[2] = d4.z; dd[3] = d4.w;
            cnt = 4;
        } else {
            cnt = e - i0;
            for (int t = 0; t < cnt; t++) { ss[t] = src[i0 + t]; dd[t] = dst[i0 + t]; }
        }
        for (int t = 0; t < cnt; t++) {
            int s = ss[t], d = dd[t];
            atomicAdd(&g_deg[d], 1);
            if (s == d) continue;  // merges with diagonal in coalesce
            unsigned long long key =
                ((unsigned long long)(unsigned)d << 32) | (unsigned)s;
            unsigned h = (unsigned)((key * 0x9E3779B97F4A7C15ull) >> (64 - HASH_BITS));
            for (;;) {
                unsigned long long old = atomicCAS(&g_hash[h], HEMPTY, key);
                if (old == HEMPTY) { atomicAdd(&g_cnt[d], 1); break; }
                if (old == key) break;
                h = (h + 1) & HASH_MASK;
            }
        }
    }
}

// ---------------- scan pass 1: per-block exclusive + block sums ----------------
__global__ void scan1_kernel(int n) {
    __shared__ int sh[1024];
    int t = threadIdx.x;
    int i = blockIdx.x * 1024 + t;
    int v = (i < n) ? g_deg[i] : 0;
    sh[t] = v;
    __syncthreads();
    for (int off = 1; off < 1024; off <<= 1) {
        int u = (t >= off) ? sh[t - off] : 0;
        __syncthreads();
        sh[t] += u;
        __syncthreads();
    }
    if (i < n) g_rowptr[i] = sh[t] - v;
    if (t == 1023) g_bsum[blockIdx.x] = sh[1023];
}

// ---------------- scan pass 2 (fused): inline block-sum prefix + cursor + norm ----------------
__global__ void scan3_kernel(int n, int nb) {
    __shared__ int shp[128], sht[128];
    int t = threadIdx.x;
    if (t < 128) {
        int vp = 0, vt = 0;
        if (t < nb) {
            int bsv = g_bsum[t];
            vt = bsv;
            if (t < (int)blockIdx.x) vp = bsv;
        }
        shp[t] = vp; sht[t] = vt;
    }
    __syncthreads();
    for (int off = 64; off > 0; off >>= 1) {
        if (t < off) { shp[t] += shp[t + off]; sht[t] += sht[t + off]; }
        __syncthreads();
    }
    int prefix = shp[0];

    int i = blockIdx.x * 1024 + t;
    if (i < n) {
        int r = g_rowptr[i] + prefix;
        g_rowptr[i] = r;
        g_cursor[i] = r;
        g_norm[i] = 1.0f / (float)(1 + g_cnt[i]);
    }
    if (blockIdx.x == gridDim.x - 1 && t == 0) g_rowptr[n] = sht[0];
}

// ---------------- CSR scatter (4 edges/thread) ----------------
__global__ void scatter_kernel(const int* __restrict__ src,
                               const int* __restrict__ dst, int e) {
    int i0 = (blockIdx.x * blockDim.x + threadIdx.x) * 4;
    if (i0 >= e) return;
    if (i0 + 4 <= e) {
        int4 s4 = *(const int4*)(src + i0);
        int4 d4 = *(const int4*)(dst + i0);
        int p0 = atomicAdd(&g_cursor[d4.x], 1); g_col[p0] = s4.x;
        int p1 = atomicAdd(&g_cursor[d4.y], 1); g_col[p1] = s4.y;
        int p2 = atomicAdd(&g_cursor[d4.z], 1); g_col[p2] = s4.z;
        int p3 = atomicAdd(&g_cursor[d4.w], 1); g_col[p3] = s4.w;
    } else {
        for (int i = i0; i < e; i++) {
            int p = atomicAdd(&g_cursor[dst[i]], 1);
            g_col[p] = src[i];
        }
    }
}

// ---------------- layer-1 aggregation + combine + relu (fp16 gather, fp32 accumulate) ----------------
__global__ void agg1_kernel(const __half* __restrict__ h,
                            const float* __restrict__ wpan,
                            float* __restrict__ out, int n) {
    int wid = (blockIdx.x * blockDim.x + threadIdx.x) >> 5;
    int lane = threadIdx.x & 31;
    if (wid >= n) return;
    int lo = g_rowptr[wid], hi = g_rowptr[wid + 1];
    const __half2* h2 = (const __half2*)h;
    float ax = 0.f, ay = 0.f;
    int j = lo;
    for (; j + 1 < hi; j += 2) {
        int s0 = g_col[j], s1 = g_col[j + 1];
        float2 f0 = __half22float2(h2[(size_t)s0 * 32 + lane]);
        float2 f1 = __half22float2(h2[(size_t)s1 * 32 + lane]);
        ax += f0.x + f1.x;
        ay += f0.y + f1.y;
    }
    if (j < hi) {
        float2 f = __half22float2(h2[(size_t)g_col[j] * 32 + lane]);
        ax += f.x; ay += f.y;
    }
    float w0 = wpan[0];
    float w01 = w0 * wpan[1];
    float nm = g_norm[wid];
    float2 hv = __half22float2(h2[(size_t)wid * 32 + lane]);
    float ox = fmaxf(nm * (w0 * hv.x + w01 * ax), 0.f);
    float oy = fmaxf(nm * (w0 * hv.y + w01 * ay), 0.f);
    ((float2*)out)[(size_t)wid * 32 + lane] = make_float2(ox, oy);
}

// ---------------- layer-2 linear (packed f32x2): h2 = fp16( mid @ W2 + b2 ) ----------------
__global__ __launch_bounds__(256) void lin2_kernel(const float* __restrict__ x,
                                                   const float* __restrict__ W,
                                                   const float* __restrict__ b,
                                                   __half* __restrict__ out, int n) {
    __shared__ float Ws[64 * HID];
    __shared__ float bs[HID];
    for (int i = threadIdx.x; i < (64 * HID) / 4; i += blockDim.x)
        ((float4*)Ws)[i] = ((const float4*)W)[i];
    if (threadIdx.x < HID) bs[threadIdx.x] = b[threadIdx.x];
    __syncthreads();

    int row = blockIdx.x * blockDim.x + threadIdx.x;
    if (row >= n) return;

    unsigned long long acc2[32];   // 32 packed pairs = 64 fp32 accumulators
#pragma unroll
    for (int c = 0; c < 32; c++) acc2[c] = 0ull;

    const float4* xr = (const float4*)(x + (size_t)row * 64);
#pragma unroll
    for (int k4 = 0; k4 < 16; k4++) {
        float4 xv = xr[k4];
        float xk[4] = {xv.x, xv.y, xv.z, xv.w};
#pragma unroll
        for (int kk = 0; kk < 4; kk++) {
            unsigned long long xp = pack2(xk[kk], xk[kk]);
            const ulonglong2* wr = (const ulonglong2*)(Ws + (k4 * 4 + kk) * HID);
#pragma unroll
            for (int c = 0; c < 16; c++) {
                ulonglong2 w = wr[c];
                acc2[2 * c + 0] = fma2(xp, w.x, acc2[2 * c + 0]);
                acc2[2 * c + 1] = fma2(xp, w.y, acc2[2 * c + 1]);
            }
        }
    }
    __half2 hv[32];
#pragma unroll
    for (int c = 0; c < 32; c++) {
        float2 v = unpack2(acc2[c]);
        hv[c] = __floats2half2_rn(v.x + bs[2 * c], v.y + bs[2 * c + 1]);
    }
    uint4* o = (uint4*)(out + (size_t)row * HID);
#pragma unroll
    for (int c = 0; c < 8; c++) o[c] = ((uint4*)hv)[c];
}

// ---------------- FUSED layer-2 aggregation + classifier halves (fp16 gather) ----------------
__global__ void agg2pq_kernel(const __half* __restrict__ h,
                              const float* __restrict__ wpan,
                              const float* __restrict__ wc, int n) {
    int wid = (blockIdx.x * blockDim.x + threadIdx.x) >> 5;
    int lane = threadIdx.x & 31;
    if (wid >= n) return;
    int lo = g_rowptr[wid], hi = g_rowptr[wid + 1];
    const __half2* h2 = (const __half2*)h;
    float ax = 0.f, ay = 0.f;
    int j = lo;
    for (; j + 1 < hi; j += 2) {
        int s0 = g_col[j], s1 = g_col[j + 1];
        float2 f0 = __half22float2(h2[(size_t)s0 * 32 + lane]);
        float2 f1 = __half22float2(h2[(size_t)s1 * 32 + lane]);
        ax += f0.x + f1.x;
        ay += f0.y + f1.y;
    }
    if (j < hi) {
        float2 f = __half22float2(h2[(size_t)g_col[j] * 32 + lane]);
        ax += f.x; ay += f.y;
    }
    float w0 = wpan[0];
    float w01 = w0 * wpan[1];
    float nm = g_norm[wid];
    float2 hv = __half22float2(h2[(size_t)wid * 32 + lane]);
    float ox = nm * (w0 * hv.x + w01 * ax);   // h_final[2*lane]
    float oy = nm * (w0 * hv.y + w01 * ay);   // h_final[2*lane+1]

    // wc is [128,2] row-major; rows 0..63 = src half, 64..127 = dst half
    int c0 = 2 * lane, c1 = 2 * lane + 1;
    float p0 = ox * __ldg(&wc[c0 * 2 + 0]) + oy * __ldg(&wc[c1 * 2 + 0]);
    float p1 = ox * __ldg(&wc[c0 * 2 + 1]) + oy * __ldg(&wc[c1 * 2 + 1]);
    float q0 = ox * __ldg(&wc[(64 + c0) * 2 + 0]) + oy * __ldg(&wc[(64 + c1) * 2 + 0]);
    float q1 = ox * __ldg(&wc[(64 + c0) * 2 + 1]) + oy * __ldg(&wc[(64 + c1) * 2 + 1]);
#pragma unroll
    for (int off = 16; off > 0; off >>= 1) {
        p0 += __shfl_down_sync(0xffffffffu, p0, off);
        p1 += __shfl_down_sync(0xffffffffu, p1, off);
        q0 += __shfl_down_sync(0xffffffffu, q0, off);
        q1 += __shfl_down_sync(0xffffffffu, q1, off);
    }
    if (lane == 0) g_pq[wid] = make_float4(p0, p1, q0, q1);
}

// ---------------- per-edge output (4 edges/thread) ----------------
__global__ void edge_kernel(const int* __restrict__ src,
                            const int* __restrict__ dst,
                            const float* __restrict__ bc,
                            float* __restrict__ out, int e) {
    int i0 = (blockIdx.x * blockDim.x + threadIdx.x) * 4;
    if (i0 >= e) return;
    float b0 = __ldg(&bc[0]), b1 = __ldg(&bc[1]);
    if (i0 + 4 <= e) {
        int4 s4 = *(const int4*)(src + i0);
        int4 d4 = *(const int4*)(dst + i0);
        float4 pa = g_pq[s4.x], qa = g_pq[d4.x];
        float4 pb = g_pq[s4.y], qb = g_pq[d4.y];
        float4 pc = g_pq[s4.z], qc = g_pq[d4.z];
        float4 pd = g_pq[s4.w], qd = g_pq[d4.w];
        float4 o0, o1;
        o0.x = pa.x + qa.z + b0; o0.y = pa.y + qa.w + b1;
        o0.z = pb.x + qb.z + b0; o0.w = pb.y + qb.w + b1;
        o1.x = pc.x + qc.z + b0; o1.y = pc.y + qc.w + b1;
        o1.z = pd.x + qd.z + b0; o1.w = pd.y + qd.w + b1;
        ((float4*)(out + (size_t)i0 * 2))[0] = o0;
        ((float4*)(out + (size_t)i0 * 2))[1] = o1;
    } else {
        for (int i = i0; i < e; i++) {
            float4 ps = g_pq[src[i]];
            float4 qd = g_pq[dst[i]];
            ((float2*)out)[i] = make_float2(ps.x + qd.z + b0, ps.y + qd.w + b1);
        }
    }
}

// ---------------- launch ----------------
extern "C" void kernel_launch(void* const* d_in, const int* in_sizes, int n_in,
                              void* d_out, int out_size) {
    const float* x   = (const float*)d_in[0];
    const int*   ei  = (const int*)d_in[1];
    const float* w1  = (const float*)d_in[2];
    const float* b1  = (const float*)d_in[3];
    const float* p1  = (const float*)d_in[4];  // w1_pan
    const float* w2  = (const float*)d_in[5];
    const float* b2  = (const float*)d_in[6];
    const float* p2  = (const float*)d_in[7];  // w2_pan
    const float* wc  = (const float*)d_in[8];
    const float* bc  = (const float*)d_in[9];
    float* out = (float*)d_out;

    int n = in_sizes[0] / 128;
    int e = in_sizes[1] / 2;
    const int* src = ei;
    const int* dst = ei + e;

    __half* h1 = nullptr; __half* h2 = nullptr; float* mid = nullptr;
    cudaGetSymbolAddress((void**)&h1, g_h1);
    cudaGetSymbolAddress((void**)&h2, g_h2);
    cudaGetSymbolAddress((void**)&mid, g_mid);

    int nb256 = (n + 255) / 256;
    int nb1024 = (n + 1023) / 1024;
    int ebv = (e / 4 + 255) / 256 + 1;        // 4 edges/thread blocks (covers tail)
    int nbLin = (2 * n + 255) / 256;          // half-row lin1 blocks

    init_kernel<<<2048, 256>>>(n);
    fused_lin1_hist_kernel<<<nbLin + ebv, 256>>>(x, w1, b1, src, dst, h1, n, e, nbLin);
    scan1_kernel<<<nb1024, 1024>>>(n);
    scan3_kernel<<<nb1024, 1024>>>(n, nb1024);
    scatter_kernel<<<ebv, 256>>>(src, dst, e);

    agg1_kernel<<<(n * 32 + 255) / 256, 256>>>(h1, p1, mid, n);       // layer-1 agg + relu
    lin2_kernel<<<nb256, 256>>>(mid, w2, b2, h2, n);                  // layer-2 lin
    agg2pq_kernel<<<(n * 32 + 255) / 256, 256>>>(h2, p2, wc, n);      // layer-2 agg + pq
    edge_kernel<<<ebv, 256>>>(src, dst, bc, out, e);
}

// round 7
// speedup vs baseline: 1.6123x; 1.0807x over previous
#include <cuda_runtime.h>
#include <cuda_fp16.h>

#define NMAX 100000
#define EMAX 1600000
#define HID 64

// ---------------- packed f32x2 helpers (sm_103a dual-fp32 pipe) ----------------
__device__ __forceinline__ unsigned long long pack2(float lo, float hi) {
    unsigned long long r;
    asm("mov.b64 %0, {%1, %2};" : "=l"(r) : "f"(lo), "f"(hi));
    return r;
}
__device__ __forceinline__ float2 unpack2(unsigned long long v) {
    float lo, hi;
    asm("mov.b64 {%0, %1}, %2;" : "=f"(lo), "=f"(hi) : "l"(v));
    return make_float2(lo, hi);
}
__device__ __forceinline__ unsigned long long fma2(unsigned long long a,
                                                   unsigned long long b,
                                                   unsigned long long c) {
    unsigned long long d;
    asm("fma.rn.f32x2 %0, %1, %2, %3;" : "=l"(d) : "l"(a), "l"(b), "l"(c));
    return d;
}

// ---------------- scratch (device globals: allocation-free rule) ----------------
__device__ int    g_deg[NMAX];
__device__ int    g_rowptr[NMAX + 1];
__device__ int    g_cursor[NMAX];
__device__ int    g_bsum[1024];
__device__ int    g_col[EMAX];
__device__ float  g_norm[NMAX];
__device__ __half g_h1[(size_t)NMAX * HID];   // lin1 out (fp16 gather table)
__device__ float  g_mid[(size_t)NMAX * HID];  // agg1 out (fp32, lin2 input)
__device__ __half g_h2[(size_t)NMAX * HID];   // lin2 out (fp16 gather table)
__device__ float4 g_pq[NMAX];

// ---------------- FUSED: lin1 (half-row per thread, f32x2) + degree histogram ----------------
__global__ __launch_bounds__(256) void fused_lin1_hist_kernel(
    const float* __restrict__ x, const float* __restrict__ W,
    const float* __restrict__ b,
    const int* __restrict__ dst,
    __half* __restrict__ out, int n, int e, int nbLin)
{
    __shared__ float Ws[128 * HID];   // 32 KB
    __shared__ float bs[HID];

    if (blockIdx.x < nbLin) {
        // -------- GEMM branch: 2 threads per row, 32 cols each, packed f32x2 --------
        for (int i = threadIdx.x; i < (128 * HID) / 4; i += 256)
            ((float4*)Ws)[i] = ((const float4*)W)[i];
        if (threadIdx.x < HID) bs[threadIdx.x] = b[threadIdx.x];
        __syncthreads();

        int gid = blockIdx.x * 256 + threadIdx.x;
        int row = gid >> 1;
        int half = gid & 1;
        if (row >= n) return;

        unsigned long long acc2[16];
#pragma unroll
        for (int c = 0; c < 16; c++) acc2[c] = 0ull;

        const float4* xr = (const float4*)(x + (size_t)row * 128);
        int cbase = half * 32;
#pragma unroll
        for (int k4 = 0; k4 < 32; k4++) {
            float4 xv = xr[k4];
            float xk[4] = {xv.x, xv.y, xv.z, xv.w};
#pragma unroll
            for (int kk = 0; kk < 4; kk++) {
                unsigned long long xp = pack2(xk[kk], xk[kk]);
                const ulonglong2* wr =
                    (const ulonglong2*)(Ws + (k4 * 4 + kk) * HID + cbase);
#pragma unroll
                for (int c = 0; c < 8; c++) {
                    ulonglong2 w = wr[c];
                    acc2[2 * c + 0] = fma2(xp, w.x, acc2[2 * c + 0]);
                    acc2[2 * c + 1] = fma2(xp, w.y, acc2[2 * c + 1]);
                }
            }
        }
        __half2 hv[16];
#pragma unroll
        for (int c = 0; c < 16; c++) {
            float2 v = unpack2(acc2[c]);
            hv[c] = __floats2half2_rn(v.x + bs[cbase + 2 * c],
                                      v.y + bs[cbase + 2 * c + 1]);
        }
        uint4* o = (uint4*)(out + (size_t)row * HID + cbase);
        o[0] = ((uint4*)hv)[0];
        o[1] = ((uint4*)hv)[1];
        o[2] = ((uint4*)hv)[2];
        o[3] = ((uint4*)hv)[3];
    } else {
        // -------- degree histogram only, 4 edges per thread --------
        int bid = blockIdx.x - nbLin;
        int i0 = (bid * 256 + threadIdx.x) * 4;
        if (i0 >= e) return;
        if (i0 + 4 <= e) {
            int4 d4 = *(const int4*)(dst + i0);
            atomicAdd(&g_deg[d4.x], 1);
            atomicAdd(&g_deg[d4.y], 1);
            atomicAdd(&g_deg[d4.z], 1);
            atomicAdd(&g_deg[d4.w], 1);
        } else {
            for (int i = i0; i < e; i++) atomicAdd(&g_deg[dst[i]], 1);
        }
    }
}

// ---------------- scan pass 1: per-block exclusive + block sums ----------------
__global__ void scan1_kernel(int n) {
    __shared__ int sh[1024];
    int t = threadIdx.x;
    int i = blockIdx.x * 1024 + t;
    int v = (i < n) ? g_deg[i] : 0;
    sh[t] = v;
    __syncthreads();
    for (int off = 1; off < 1024; off <<= 1) {
        int u = (t >= off) ? sh[t - off] : 0;
        __syncthreads();
        sh[t] += u;
        __syncthreads();
    }
    if (i < n) g_rowptr[i] = sh[t] - v;
    if (t == 1023) g_bsum[blockIdx.x] = sh[1023];
}

// ---------------- scan pass 2 (fused): inline block-sum prefix + cursor ----------------
__global__ void scan3_kernel(int n, int nb) {
    __shared__ int shp[128], sht[128];
    int t = threadIdx.x;
    if (t < 128) {
        int vp = 0, vt = 0;
        if (t < nb) {
            int bsv = g_bsum[t];
            vt = bsv;
            if (t < (int)blockIdx.x) vp = bsv;
        }
        shp[t] = vp; sht[t] = vt;
    }
    __syncthreads();
    for (int off = 64; off > 0; off >>= 1) {
        if (t < off) { shp[t] += shp[t + off]; sht[t] += sht[t + off]; }
        __syncthreads();
    }
    int prefix = shp[0];

    int i = blockIdx.x * 1024 + t;
    if (i < n) {
        int r = g_rowptr[i] + prefix;
        g_rowptr[i] = r;
        g_cursor[i] = r;
    }
    if (blockIdx.x == gridDim.x - 1 && t == 0) g_rowptr[n] = sht[0];
}

// ---------------- CSR scatter (4 edges/thread) ----------------
__global__ void scatter_kernel(const int* __restrict__ src,
                               const int* __restrict__ dst, int e) {
    int i0 = (blockIdx.x * blockDim.x + threadIdx.x) * 4;
    if (i0 >= e) return;
    if (i0 + 4 <= e) {
        int4 s4 = *(const int4*)(src + i0);
        int4 d4 = *(const int4*)(dst + i0);
        int p0 = atomicAdd(&g_cursor[d4.x], 1); g_col[p0] = s4.x;
        int p1 = atomicAdd(&g_cursor[d4.y], 1); g_col[p1] = s4.y;
        int p2 = atomicAdd(&g_cursor[d4.z], 1); g_col[p2] = s4.z;
        int p3 = atomicAdd(&g_cursor[d4.w], 1); g_col[p3] = s4.w;
    } else {
        for (int i = i0; i < e; i++) {
            int p = atomicAdd(&g_cursor[dst[i]], 1);
            g_col[p] = src[i];
        }
    }
}

// ---------------- layer-1 agg + in-warp distinct count (match_any) + norm + relu ----------------
__global__ void agg1_kernel(const __half* __restrict__ h,
                            const float* __restrict__ wpan,
                            float* __restrict__ out, int n) {
    int wid = (blockIdx.x * blockDim.x + threadIdx.x) >> 5;
    int lane = threadIdx.x & 31;
    if (wid >= n) return;
    int lo = g_rowptr[wid], hi = g_rowptr[wid + 1];

    // ---- distinct in-neighbor count (coalesce semantics), warp-cooperative ----
    int cnt = 1;  // diagonal
    for (int c0 = lo; c0 < hi; c0 += 32) {
        int idx = c0 + lane;
        int v = (idx < hi) ? g_col[idx] : (-1 - lane);  // unique sentinels never match
        bool valid = (idx < hi) && (v != wid);          // self-loop merges with diagonal
        unsigned m = __match_any_sync(0xffffffffu, v);
        bool lead = valid && ((m & ((1u << lane) - 1u)) == 0u);
        if (lead && c0 > lo) {   // rare (deg>32): check earlier chunks serially
            for (int j = lo; j < c0; j++)
                if (g_col[j] == v) { lead = false; break; }
        }
        cnt += __popc(__ballot_sync(0xffffffffu, lead));
    }
    float nm = 1.0f / (float)cnt;
    if (lane == 0) g_norm[wid] = nm;

    // ---- gather-reduce (fp16 gather, fp32 accumulate) ----
    const __half2* h2 = (const __half2*)h;
    float ax = 0.f, ay = 0.f;
    int j = lo;
    for (; j + 1 < hi; j += 2) {
        int s0 = g_col[j], s1 = g_col[j + 1];
        float2 f0 = __half22float2(h2[(size_t)s0 * 32 + lane]);
        float2 f1 = __half22float2(h2[(size_t)s1 * 32 + lane]);
        ax += f0.x + f1.x;
        ay += f0.y + f1.y;
    }
    if (j < hi) {
        float2 f = __half22float2(h2[(size_t)g_col[j] * 32 + lane]);
        ax += f.x; ay += f.y;
    }
    float w0 = wpan[0];
    float w01 = w0 * wpan[1];
    float2 hv = __half22float2(h2[(size_t)wid * 32 + lane]);
    float ox = fmaxf(nm * (w0 * hv.x + w01 * ax), 0.f);
    float oy = fmaxf(nm * (w0 * hv.y + w01 * ay), 0.f);
    ((float2*)out)[(size_t)wid * 32 + lane] = make_float2(ox, oy);
}

// ---------------- layer-2 linear (packed f32x2): h2 = fp16( mid @ W2 + b2 ) ----------------
__global__ __launch_bounds__(256) void lin2_kernel(const float* __restrict__ x,
                                                   const float* __restrict__ W,
                                                   const float* __restrict__ b,
                                                   __half* __restrict__ out, int n) {
    __shared__ float Ws[64 * HID];
    __shared__ float bs[HID];
    for (int i = threadIdx.x; i < (64 * HID) / 4; i += blockDim.x)
        ((float4*)Ws)[i] = ((const float4*)W)[i];
    if (threadIdx.x < HID) bs[threadIdx.x] = b[threadIdx.x];
    __syncthreads();

    int row = blockIdx.x * blockDim.x + threadIdx.x;
    if (row >= n) return;

    unsigned long long acc2[32];
#pragma unroll
    for (int c = 0; c < 32; c++) acc2[c] = 0ull;

    const float4* xr = (const float4*)(x + (size_t)row * 64);
#pragma unroll
    for (int k4 = 0; k4 < 16; k4++) {
        float4 xv = xr[k4];
        float xk[4] = {xv.x, xv.y, xv.z, xv.w};
#pragma unroll
        for (int kk = 0; kk < 4; kk++) {
            unsigned long long xp = pack2(xk[kk], xk[kk]);
            const ulonglong2* wr = (const ulonglong2*)(Ws + (k4 * 4 + kk) * HID);
#pragma unroll
            for (int c = 0; c < 16; c++) {
                ulonglong2 w = wr[c];
                acc2[2 * c + 0] = fma2(xp, w.x, acc2[2 * c + 0]);
                acc2[2 * c + 1] = fma2(xp, w.y, acc2[2 * c + 1]);
            }
        }
    }
    __half2 hv[32];
#pragma unroll
    for (int c = 0; c < 32; c++) {
        float2 v = unpack2(acc2[c]);
        hv[c] = __floats2half2_rn(v.x + bs[2 * c], v.y + bs[2 * c + 1]);
    }
    uint4* o = (uint4*)(out + (size_t)row * HID);
#pragma unroll
    for (int c = 0; c < 8; c++) o[c] = ((uint4*)hv)[c];
}

// ---------------- FUSED layer-2 aggregation + classifier halves (fp16 gather) ----------------
__global__ void agg2pq_kernel(const __half* __restrict__ h,
                              const float* __restrict__ wpan,
                              const float* __restrict__ wc, int n) {
    int wid = (blockIdx.x * blockDim.x + threadIdx.x) >> 5;
    int lane = threadIdx.x & 31;
    if (wid >= n) return;
    int lo = g_rowptr[wid], hi = g_rowptr[wid + 1];
    const __half2* h2 = (const __half2*)h;
    float ax = 0.f, ay = 0.f;
    int j = lo;
    for (; j + 1 < hi; j += 2) {
        int s0 = g_col[j], s1 = g_col[j + 1];
        float2 f0 = __half22float2(h2[(size_t)s0 * 32 + lane]);
        float2 f1 = __half22float2(h2[(size_t)s1 * 32 + lane]);
        ax += f0.x + f1.x;
        ay += f0.y + f1.y;
    }
    if (j < hi) {
        float2 f = __half22float2(h2[(size_t)g_col[j] * 32 + lane]);
        ax += f.x; ay += f.y;
    }
    float w0 = wpan[0];
    float w01 = w0 * wpan[1];
    float nm = g_norm[wid];
    float2 hv = __half22float2(h2[(size_t)wid * 32 + lane]);
    float ox = nm * (w0 * hv.x + w01 * ax);   // h_final[2*lane]
    float oy = nm * (w0 * hv.y + w01 * ay);   // h_final[2*lane+1]

    // wc is [128,2] row-major; rows 0..63 = src half, 64..127 = dst half
    int c0 = 2 * lane, c1 = 2 * lane + 1;
    float p0 = ox * __ldg(&wc[c0 * 2 + 0]) + oy * __ldg(&wc[c1 * 2 + 0]);
    float p1 = ox * __ldg(&wc[c0 * 2 + 1]) + oy * __ldg(&wc[c1 * 2 + 1]);
    float q0 = ox * __ldg(&wc[(64 + c0) * 2 + 0]) + oy * __ldg(&wc[(64 + c1) * 2 + 0]);
    float q1 = ox * __ldg(&wc[(64 + c0) * 2 + 1]) + oy * __ldg(&wc[(64 + c1) * 2 + 1]);
#pragma unroll
    for (int off = 16; off > 0; off >>= 1) {
        p0 += __shfl_down_sync(0xffffffffu, p0, off);
        p1 += __shfl_down_sync(0xffffffffu, p1, off);
        q0 += __shfl_down_sync(0xffffffffu, q0, off);
        q1 += __shfl_down_sync(0xffffffffu, q1, off);
    }
    if (lane == 0) g_pq[wid] = make_float4(p0, p1, q0, q1);
}

// ---------------- per-edge output (4 edges/thread) ----------------
__global__ void edge_kernel(const int* __restrict__ src,
                            const int* __restrict__ dst,
                            const float* __restrict__ bc,
                            float* __restrict__ out, int e) {
    int i0 = (blockIdx.x * blockDim.x + threadIdx.x) * 4;
    if (i0 >= e) return;
    float b0 = __ldg(&bc[0]), b1 = __ldg(&bc[1]);
    if (i0 + 4 <= e) {
        int4 s4 = *(const int4*)(src + i0);
        int4 d4 = *(const int4*)(dst + i0);
        float4 pa = g_pq[s4.x], qa = g_pq[d4.x];
        float4 pb = g_pq[s4.y], qb = g_pq[d4.y];
        float4 pc = g_pq[s4.z], qc = g_pq[d4.z];
        float4 pd = g_pq[s4.w], qd = g_pq[d4.w];
        float4 o0, o1;
        o0.x = pa.x + qa.z + b0; o0.y = pa.y + qa.w + b1;
        o0.z = pb.x + qb.z + b0; o0.w = pb.y + qb.w + b1;
        o1.x = pc.x + qc.z + b0; o1.y = pc.y + qc.w + b1;
        o1.z = pd.x + qd.z + b0; o1.w = pd.y + qd.w + b1;
        ((float4*)(out + (size_t)i0 * 2))[0] = o0;
        ((float4*)(out + (size_t)i0 * 2))[1] = o1;
    } else {
        for (int i = i0; i < e; i++) {
            float4 ps = g_pq[src[i]];
            float4 qd = g_pq[dst[i]];
            ((float2*)out)[i] = make_float2(ps.x + qd.z + b0, ps.y + qd.w + b1);
        }
    }
}

// ---------------- launch ----------------
extern "C" void kernel_launch(void* const* d_in, const int* in_sizes, int n_in,
                              void* d_out, int out_size) {
    const float* x   = (const float*)d_in[0];
    const int*   ei  = (const int*)d_in[1];
    const float* w1  = (const float*)d_in[2];
    const float* b1  = (const float*)d_in[3];
    const float* p1  = (const float*)d_in[4];  // w1_pan
    const float* w2  = (const float*)d_in[5];
    const float* b2  = (const float*)d_in[6];
    const float* p2  = (const float*)d_in[7];  // w2_pan
    const float* wc  = (const float*)d_in[8];
    const float* bc  = (const float*)d_in[9];
    float* out = (float*)d_out;

    int n = in_sizes[0] / 128;
    int e = in_sizes[1] / 2;
    const int* src = ei;
    const int* dst = ei + e;

    __half* h1 = nullptr; __half* h2 = nullptr; float* mid = nullptr;
    int* degPtr = nullptr;
    cudaGetSymbolAddress((void**)&h1, g_h1);
    cudaGetSymbolAddress((void**)&h2, g_h2);
    cudaGetSymbolAddress((void**)&mid, g_mid);
    cudaGetSymbolAddress((void**)&degPtr, g_deg);

    int nb256 = (n + 255) / 256;
    int nb1024 = (n + 1023) / 1024;
    int ebv = (e / 4 + 255) / 256 + 1;        // 4 edges/thread blocks (covers tail)
    int nbLin = (2 * n + 255) / 256;          // half-row lin1 blocks

    cudaMemsetAsync(degPtr, 0, (size_t)n * sizeof(int));
    fused_lin1_hist_kernel<<<nbLin + ebv, 256>>>(x, w1, b1, dst, h1, n, e, nbLin);
    scan1_kernel<<<nb1024, 1024>>>(n);
    scan3_kernel<<<nb1024, 1024>>>(n, nb1024);
    scatter_kernel<<<ebv, 256>>>(src, dst, e);

    agg1_kernel<<<(n * 32 + 255) / 256, 256>>>(h1, p1, mid, n);       // agg1 + distinct/norm + relu
    lin2_kernel<<<nb256, 256>>>(mid, w2, b2, h2, n);                  // layer-2 lin
    agg2pq_kernel<<<(n * 32 + 255) / 256, 256>>>(h2, p2, wc, n);      // layer-2 agg + pq
    edge_kernel<<<ebv, 256>>>(src, dst, bc, out, e);
}